// round 10
// baseline (speedup 1.0000x reference)
#include <cuda_runtime.h>
#include <cuda_bf16.h>
#include <cstdint>

#define NN   8192
#define DIN  512
#define DOUT 256
#define KSLICES 2
#define KSL  (NN / KSLICES)     // 4096 k per slice
#define KT   64                 // k per chunk
#define NCHUNK (KSL / KT)       // 64

// ---------------- scratch (__device__ globals: allocation-free rule) --------
__device__ float          g_hW  [(size_t)NN * DOUT];      // fp32 hW (for f1f2)
__device__ float          g_f1  [NN];
__device__ float          g_f2  [NN];
__device__ float          g_fmax;
__device__ unsigned short g_hWT [(size_t)DOUT * NN];      // hW^T fp16 [col][row]
__device__ float          g_np  [(size_t)KSLICES * NN * DOUT]; // partial numerators
__device__ float          g_zp  [KSLICES * NN];                // partial Z

// ---------------- helpers ---------------------------------------------------
__device__ __forceinline__ uint32_t smem_u32(const void* p) {
    uint32_t a;
    asm("{ .reg .u64 t; cvta.to.shared.u64 t, %1; cvt.u32.u64 %0, t; }"
        : "=r"(a) : "l"(p));
    return a;
}
__device__ __forceinline__ uint32_t sw128(uint32_t off) {
    return off ^ ((off >> 3) & 0x70);
}
// packs (lo, hi) -> low 16 = f16(lo), high 16 = f16(hi)
__device__ __forceinline__ unsigned pack_f16x2(float lo, float hi) {
    unsigned r;
    asm("cvt.rn.f16x2.f32 %0, %1, %2;" : "=r"(r) : "f"(hi), "f"(lo));
    return r;
}
__device__ __forceinline__ void cp16(uint32_t smem, const void* g) {
    asm volatile("cp.async.cg.shared.global [%0], [%1], 16;"
                 :: "r"(smem), "l"(g));
}
__device__ __forceinline__ void cp_commit() {
    asm volatile("cp.async.commit_group;");
}
__device__ __forceinline__ void cp_wait0() {
    asm volatile("cp.async.wait_group 0;" ::: "memory");
}
__device__ __forceinline__ void ldsm4(uint32_t* r, uint32_t addr) {
    asm volatile("ldmatrix.sync.aligned.m8n8.x4.shared.b16 {%0,%1,%2,%3}, [%4];"
                 : "=r"(r[0]), "=r"(r[1]), "=r"(r[2]), "=r"(r[3]) : "r"(addr));
}
__device__ __forceinline__ void mma16816(float* c, const uint32_t* a,
                                         uint32_t b0, uint32_t b1) {
    asm volatile(
        "mma.sync.aligned.m16n8k16.row.col.f32.f16.f16.f32 "
        "{%0,%1,%2,%3},{%4,%5,%6,%7},{%8,%9},{%0,%1,%2,%3};"
        : "+f"(c[0]), "+f"(c[1]), "+f"(c[2]), "+f"(c[3])
        : "r"(a[0]), "r"(a[1]), "r"(a[2]), "r"(a[3]), "r"(b0), "r"(b1));
}
#define BAR_SYNC(id, cnt) \
    asm volatile("bar.sync %0, %1;" :: "r"(id), "r"(cnt) : "memory")
#define BAR_ARRIVE(id, cnt) \
    asm volatile("bar.arrive %0, %1;" :: "r"(id), "r"(cnt) : "memory")

// ---------------------------------------------------------------------------
// Kernel A: g_hW = h @ W  (fp32)  +  epilogue: g_hWT fp16 (transposed)
// 128x64 tile, 256 threads, 8x4 micro-tile.
// ---------------------------------------------------------------------------
__global__ __launch_bounds__(256) void k_gemm_hw(
    const float* __restrict__ h, const float* __restrict__ W)
{
    __shared__ float As[32][128];  // [k][m] 16 KB
    __shared__ float Bs[32][64];   // [k][n]  8 KB

    const int tid = threadIdx.x;
    const int c0  = blockIdx.x * 64;
    const int i0  = blockIdx.y * 128;
    const int tx  = tid & 15;            // 4 cols
    const int ty  = tid >> 4;            // 8 rows

    const int li  = tid >> 1;            // 0..127 A-load row
    const int lk  = (tid & 1) * 16;      // A-load k base (16 k's)

    const int bk  = tid >> 3;            // 0..31  B-load k
    const int bc  = (tid & 7) * 8;       // B-load col (8 cols)

    float acc[8][4] = {};

    for (int k0 = 0; k0 < DIN; k0 += 32) {
        float4 a0 = *(const float4*)&h[(i0 + li) * DIN + k0 + lk];
        float4 a1 = *(const float4*)&h[(i0 + li) * DIN + k0 + lk + 4];
        float4 a2 = *(const float4*)&h[(i0 + li) * DIN + k0 + lk + 8];
        float4 a3 = *(const float4*)&h[(i0 + li) * DIN + k0 + lk + 12];
        float4 b0 = *(const float4*)&W[(k0 + bk) * DOUT + c0 + bc];
        float4 b1 = *(const float4*)&W[(k0 + bk) * DOUT + c0 + bc + 4];

        __syncthreads();
        As[lk +  0][li] = a0.x; As[lk +  1][li] = a0.y;
        As[lk +  2][li] = a0.z; As[lk +  3][li] = a0.w;
        As[lk +  4][li] = a1.x; As[lk +  5][li] = a1.y;
        As[lk +  6][li] = a1.z; As[lk +  7][li] = a1.w;
        As[lk +  8][li] = a2.x; As[lk +  9][li] = a2.y;
        As[lk + 10][li] = a2.z; As[lk + 11][li] = a2.w;
        As[lk + 12][li] = a3.x; As[lk + 13][li] = a3.y;
        As[lk + 14][li] = a3.z; As[lk + 15][li] = a3.w;
        *(float4*)&Bs[bk][bc]     = b0;
        *(float4*)&Bs[bk][bc + 4] = b1;
        __syncthreads();

        #pragma unroll
        for (int k = 0; k < 32; k++) {
            float4 af0 = *(const float4*)&As[k][ty * 8];
            float4 af1 = *(const float4*)&As[k][ty * 8 + 4];
            float4 bf  = *(const float4*)&Bs[k][tx * 4];
            float ar[8] = {af0.x, af0.y, af0.z, af0.w,
                           af1.x, af1.y, af1.z, af1.w};
            float br[4] = {bf.x, bf.y, bf.z, bf.w};
            #pragma unroll
            for (int r = 0; r < 8; r++)
                #pragma unroll
                for (int c = 0; c < 4; c++)
                    acc[r][c] = fmaf(ar[r], br[c], acc[r][c]);
        }
    }

    #pragma unroll
    for (int r = 0; r < 8; r++) {
        float4 v = make_float4(acc[r][0], acc[r][1], acc[r][2], acc[r][3]);
        *(float4*)&g_hW[(size_t)(i0 + ty * 8 + r) * DOUT + c0 + tx * 4] = v;
    }
    // transposed fp16: 8 rows per column -> one uint4
    #pragma unroll
    for (int cc = 0; cc < 4; cc++) {
        const int c = c0 + tx * 4 + cc;
        uint4 p;
        p.x = pack_f16x2(acc[0][cc], acc[1][cc]);
        p.y = pack_f16x2(acc[2][cc], acc[3][cc]);
        p.z = pack_f16x2(acc[4][cc], acc[5][cc]);
        p.w = pack_f16x2(acc[6][cc], acc[7][cc]);
        *(uint4*)(g_hWT + (size_t)c * NN + i0 + ty * 8) = p;
    }
}

// ---------------------------------------------------------------------------
// Kernel B: f1 = hW @ a[:256],  f2 = hW @ a[256:]
// ---------------------------------------------------------------------------
__global__ void k_f1f2(const float* __restrict__ a)
{
    const int row  = blockIdx.x * 8 + threadIdx.y;
    const int lane = threadIdx.x;
    const float* hw = &g_hW[(size_t)row * DOUT];

    float s1 = 0.f, s2 = 0.f;
    #pragma unroll
    for (int c = 0; c < DOUT; c += 32) {
        float v = hw[c + lane];
        s1 = fmaf(v, a[c + lane], s1);
        s2 = fmaf(v, a[DOUT + c + lane], s2);
    }
    #pragma unroll
    for (int off = 16; off; off >>= 1) {
        s1 += __shfl_xor_sync(0xffffffffu, s1, off);
        s2 += __shfl_xor_sync(0xffffffffu, s2, off);
    }
    if (lane == 0) { g_f1[row] = s1; g_f2[row] = s2; }
}

// ---------------------------------------------------------------------------
// Kernel B2: g_fmax = max(f2)
// ---------------------------------------------------------------------------
__global__ void k_fmax()
{
    __shared__ float sred[32];
    const int tid = threadIdx.x;   // 1024 threads
    float m = -1e30f;
    #pragma unroll
    for (int i = tid; i < NN; i += 1024) m = fmaxf(m, g_f2[i]);
    #pragma unroll
    for (int o = 16; o; o >>= 1) m = fmaxf(m, __shfl_xor_sync(~0u, m, o));
    if ((tid & 31) == 0) sred[tid >> 5] = m;
    __syncthreads();
    if (tid < 32) {
        float v = sred[tid];
        #pragma unroll
        for (int o = 16; o; o >>= 1) v = fmaxf(v, __shfl_xor_sync(~0u, v, o));
        if (tid == 0) g_fmax = v;
    }
}

// ---------------------------------------------------------------------------
// Kernel C: WARP-SPECIALIZED warp-MMA masked-softmax aggregation.
// 384 threads: warps 0-7 = consumers (2m x 4n of 32x64 tiles, M=64 N=256),
//              warps 8-11 = producers (adj LDG + exp + A STS + B cp.async).
// R10 fix vs R9: load_B now covers the FULL 128-byte B row (cc 0..7);
// R9 loaded only half, leaving NaN garbage in SMEM.
// Named barriers: full[s]=1+s (prod arrive 128 / cons sync 256),
//                 empty[s]=3+s (cons arrive 256 / prod sync 128), count=384.
// ---------------------------------------------------------------------------
// SMEM: [0..2KB) zbuf(128 floats); stages at 2KB: per stage A 8K | B 32K
#define ZOFF        0
#define TILE0       2048
#define STAGE_BYTES 40960
#define SMEM_TOTAL  (TILE0 + 2 * STAGE_BYTES)
#define NTH         384

__global__ __launch_bounds__(NTH, 1) void k_gat_mma(const int* __restrict__ adj)
{
    extern __shared__ __align__(1024) char smem[];
    const uint32_t sb = smem_u32(smem);

    const int tid  = threadIdx.x;
    const int lane = tid & 31;
    const int wid  = tid >> 5;     // 0..11
    const int i0   = blockIdx.x * 64;
    const int ks   = blockIdx.y;
    const int k0s  = ks * KSL;

    int AOFF[2], BOFF[2];
    #pragma unroll
    for (int s = 0; s < 2; s++) {
        AOFF[s] = TILE0 + s * STAGE_BYTES;
        BOFF[s] = AOFF[s] + 8192;
    }

    if (wid < 8) {
        // =================== CONSUMERS (256 threads) =======================
        const int wm = wid & 1;      // warp row (32 rows)
        const int wn = wid >> 1;     // warp col (64 cols)
        const int aRow = lane & 15;
        const int aH   = lane >> 4;
        const int bRow = (lane & 7) | ((lane >> 4) << 3);
        const int bH   = (lane >> 3) & 1;

        float acc[2][8][4];
        #pragma unroll
        for (int mt = 0; mt < 2; mt++)
            #pragma unroll
            for (int nt = 0; nt < 8; nt++)
                #pragma unroll
                for (int q = 0; q < 4; q++) acc[mt][nt][q] = 0.f;

        #pragma unroll 1
        for (int jt = 0; jt < NCHUNK; ++jt) {
            const int s = jt & 1;
            BAR_SYNC(1 + s, NTH);            // wait stage s full

            #pragma unroll
            for (int kk = 0; kk < 4; kk++) {
                uint32_t ah[2][4];
                #pragma unroll
                for (int mt = 0; mt < 2; mt++)
                    ldsm4(ah[mt], sb + AOFF[s] + sw128((uint32_t)(
                        (wm * 32 + mt * 16 + aRow) * 128 + kk * 32 + aH * 16)));
                uint32_t bh[4][4];
                #pragma unroll
                for (int p = 0; p < 4; p++)
                    ldsm4(bh[p], sb + BOFF[s] + sw128((uint32_t)(
                        (wn * 64 + p * 16 + bRow) * 128 + kk * 32 + bH * 16)));
                #pragma unroll
                for (int mt = 0; mt < 2; mt++)
                    #pragma unroll
                    for (int p = 0; p < 4; p++) {
                        mma16816(acc[mt][2 * p],     ah[mt], bh[p][0], bh[p][1]);
                        mma16816(acc[mt][2 * p + 1], ah[mt], bh[p][2], bh[p][3]);
                    }
            }

            BAR_ARRIVE(3 + s, NTH);          // mark stage s empty
        }

        // epilogue: partial numerators
        float* npb = g_np + (size_t)ks * NN * DOUT;
        const int g  = lane >> 2;
        const int tg = lane & 3;
        #pragma unroll
        for (int mt = 0; mt < 2; mt++)
            #pragma unroll
            for (int nt = 0; nt < 8; nt++) {
                const int r0  = i0 + wm * 32 + mt * 16 + g;
                const int col = wn * 64 + nt * 8 + tg * 2;
                *(float2*)(npb + (size_t)r0 * DOUT + col) =
                    make_float2(acc[mt][nt][0], acc[mt][nt][1]);
                *(float2*)(npb + (size_t)(r0 + 8) * DOUT + col) =
                    make_float2(acc[mt][nt][2], acc[mt][nt][3]);
            }
    } else {
        // =================== PRODUCERS (128 threads) =======================
        const int tp = tid - 256;            // 0..127
        const int iw = tp >> 1;              // row 0..63
        const int kb = (tp & 1) * 32;        // k base: 0 or 32 (32 k's)
        const float f1v  = g_f1[i0 + iw];
        const float smax = f1v + g_fmax;
        const float Mrow = fmaxf(smax, 0.2f * smax);
        float zacc = 0.f;

        const int rB0 = tp * 2;              // B rows rB0, rB0+1

        int4 pa[8];                          // adj prefetch: 32 ints
        auto prefetch_adj = [&](int jt) {
            const int4* ap = (const int4*)(adj + (size_t)(i0 + iw) * NN
                                           + k0s + jt * KT + kb);
            #pragma unroll
            for (int q = 0; q < 8; q++) pa[q] = ap[q];
        };

        auto load_B = [&](int jt, int s) {
            #pragma unroll
            for (int r = 0; r < 2; r++) {
                const int rB = rB0 + r;
                const size_t gk = (size_t)rB * NN + k0s + jt * KT;
                #pragma unroll
                for (int cc = 0; cc < 8; cc++)   // FULL 128-byte row (R10 fix)
                    cp16(sb + BOFF[s] + sw128((uint32_t)(rB * 128 + cc * 16)),
                         g_hWT + gk + cc * 8);
            }
        };

        auto gen_A_store = [&](int jt, int s) {
            const float4* fp = (const float4*)(g_f2 + k0s + jt * KT + kb);
            #pragma unroll
            for (int m = 0; m < 4; m++) {      // 4 groups of 8 k's
                int4   Aa = pa[2 * m], Ab = pa[2 * m + 1];
                float4 Fa = fp[2 * m], Fb = fp[2 * m + 1];
                const int   av[8] = {Aa.x, Aa.y, Aa.z, Aa.w,
                                     Ab.x, Ab.y, Ab.z, Ab.w};
                const float fv[8] = {Fa.x, Fa.y, Fa.z, Fa.w,
                                     Fb.x, Fb.y, Fb.z, Fb.w};
                float w[8];
                #pragma unroll
                for (int q = 0; q < 8; q++) {
                    float sv = f1v + fv[q];
                    float e  = fmaxf(sv, 0.2f * sv);
                    float we = __expf(e - Mrow);
                    w[q] = (av[q] > 0) ? we : 0.f;
                    zacc += w[q];
                }
                uint4 H;
                H.x = pack_f16x2(w[0], w[1]);
                H.y = pack_f16x2(w[2], w[3]);
                H.z = pack_f16x2(w[4], w[5]);
                H.w = pack_f16x2(w[6], w[7]);
                const uint32_t off = sw128((uint32_t)(
                    iw * 128 + kb * 2 + m * 16));
                *(uint4*)(smem + AOFF[s] + off) = H;
            }
        };

        prefetch_adj(0);

        #pragma unroll 1
        for (int jt = 0; jt < NCHUNK; ++jt) {
            const int s = jt & 1;
            if (jt >= 2) BAR_SYNC(3 + s, NTH);   // wait stage s empty
            load_B(jt, s);
            cp_commit();
            gen_A_store(jt, s);                  // consume adj regs (jt)
            if (jt + 1 < NCHUNK) prefetch_adj(jt + 1);  // LDG early; hides
            cp_wait0();                          // B(jt) arrived
            BAR_ARRIVE(1 + s, NTH);              // mark stage s full
        }

        // Z: combine the two k-half producers per row
        float* zb = (float*)(smem + ZOFF);
        zb[tp] = zacc;
        BAR_SYNC(5, 128);                        // producers only
        if (tp < 64)
            g_zp[ks * NN + i0 + tp] = zb[2 * tp] + zb[2 * tp + 1];
    }
}

// ---------------------------------------------------------------------------
// Kernel D: combine partials, softmax-normalize, ELU
// ---------------------------------------------------------------------------
__global__ void k_combine(float* __restrict__ out)
{
    const int row = blockIdx.x;
    const int c = threadIdx.x * 4;
    const float inv = 1.f / (g_zp[row] + g_zp[NN + row]);
    float4 p0 = *(const float4*)&g_np[(size_t)row * DOUT + c];
    float4 p1 = *(const float4*)&g_np[(size_t)(NN + row) * DOUT + c];
    float v[4] = {(p0.x + p1.x) * inv, (p0.y + p1.y) * inv,
                  (p0.z + p1.z) * inv, (p0.w + p1.w) * inv};
    #pragma unroll
    for (int q = 0; q < 4; q++)
        v[q] = (v[q] > 0.f) ? v[q] : expm1f(v[q]);
    *(float4*)&out[(size_t)row * DOUT + c] = make_float4(v[0], v[1], v[2], v[3]);
}

// ---------------------------------------------------------------------------
extern "C" void kernel_launch(void* const* d_in, const int* in_sizes, int n_in,
                              void* d_out, int out_size)
{
    const float* h   = (const float*)d_in[0];   // [8192, 512]
    const int*   adj = (const int*)  d_in[1];   // [8192, 8192]
    const float* W   = (const float*)d_in[2];   // [512, 256]
    const float* a   = (const float*)d_in[3];   // [512, 1]
    float* out = (float*)d_out;                 // [8192, 256]

    cudaFuncSetAttribute(k_gat_mma, cudaFuncAttributeMaxDynamicSharedMemorySize,
                         SMEM_TOTAL);

    k_gemm_hw<<<dim3(DOUT / 64, NN / 128), 256>>>(h, W);
    k_f1f2<<<NN / 8, dim3(32, 8)>>>(a);
    k_fmax<<<1, 1024>>>();
    k_gat_mma<<<dim3(NN / 64, KSLICES), NTH, SMEM_TOTAL>>>(adj);
    k_combine<<<NN, 64>>>(out);
}

// round 11
// speedup vs baseline: 1.0646x; 1.0646x over previous
#include <cuda_runtime.h>
#include <cuda_bf16.h>
#include <cstdint>

#define NN   8192
#define DIN  512
#define DOUT 256
#define KT   64                 // k per chunk (gat)
#define NCHUNK (NN / KT)        // 128
#define HNCH (DIN / KT)         // 8 chunks for hWT gemm

// ---------------- scratch (__device__ globals: allocation-free rule) --------
__device__ float          g_f1  [NN];
__device__ float          g_f2  [NN];
__device__ float          g_fmax;
__device__ float2         g_E   [NN];                    // (exp(f2), exp(.2 f2))
__device__ float          g_wa  [2 * DIN];               // W@a1, W@a2
__device__ unsigned short g_hh  [(size_t)NN * DIN];      // h fp16
__device__ unsigned short g_Wt  [(size_t)DOUT * DIN];    // W^T fp16 [c][k]
__device__ unsigned short g_hWT [(size_t)DOUT * NN];     // hW^T fp16 [c][i]

// ---------------- helpers ---------------------------------------------------
__device__ __forceinline__ uint32_t smem_u32(const void* p) {
    uint32_t a;
    asm("{ .reg .u64 t; cvta.to.shared.u64 t, %1; cvt.u32.u64 %0, t; }"
        : "=r"(a) : "l"(p));
    return a;
}
__device__ __forceinline__ uint32_t sw128(uint32_t off) {
    return off ^ ((off >> 3) & 0x70);
}
// packs (lo, hi) -> low 16 = f16(lo), high 16 = f16(hi)
__device__ __forceinline__ unsigned pack_f16x2(float lo, float hi) {
    unsigned r;
    asm("cvt.rn.f16x2.f32 %0, %1, %2;" : "=r"(r) : "f"(hi), "f"(lo));
    return r;
}
__device__ __forceinline__ void cp16(uint32_t smem, const void* g) {
    asm volatile("cp.async.cg.shared.global [%0], [%1], 16;"
                 :: "r"(smem), "l"(g));
}
__device__ __forceinline__ void cp_commit() {
    asm volatile("cp.async.commit_group;");
}
__device__ __forceinline__ void cp_wait0() {
    asm volatile("cp.async.wait_group 0;" ::: "memory");
}
__device__ __forceinline__ void ldsm4(uint32_t* r, uint32_t addr) {
    asm volatile("ldmatrix.sync.aligned.m8n8.x4.shared.b16 {%0,%1,%2,%3}, [%4];"
                 : "=r"(r[0]), "=r"(r[1]), "=r"(r[2]), "=r"(r[3]) : "r"(addr));
}
__device__ __forceinline__ void mma16816(float* c, const uint32_t* a,
                                         uint32_t b0, uint32_t b1) {
    asm volatile(
        "mma.sync.aligned.m16n8k16.row.col.f32.f16.f16.f32 "
        "{%0,%1,%2,%3},{%4,%5,%6,%7},{%8,%9},{%0,%1,%2,%3};"
        : "+f"(c[0]), "+f"(c[1]), "+f"(c[2]), "+f"(c[3])
        : "r"(a[0]), "r"(a[1]), "r"(a[2]), "r"(a[3]), "r"(b0), "r"(b1));
}

// SMEM map shared by k_hwt / k_gat: [0..2KB) scratch; 2 stages of A 8K | B 32K
#define ZOFF        0
#define TILE0       2048
#define STAGE_BYTES 40960
#define SMEM_TOTAL  (TILE0 + 2 * STAGE_BYTES)

// ---------------------------------------------------------------------------
// k_conv_h: h fp32 -> g_hh fp16
// ---------------------------------------------------------------------------
__global__ void k_conv_h(const float* __restrict__ h)
{
    const size_t i = ((size_t)blockIdx.x * 256 + threadIdx.x) * 8;
    float4 a = *(const float4*)(h + i);
    float4 b = *(const float4*)(h + i + 4);
    uint4 o;
    o.x = pack_f16x2(a.x, a.y);
    o.y = pack_f16x2(a.z, a.w);
    o.z = pack_f16x2(b.x, b.y);
    o.w = pack_f16x2(b.z, b.w);
    *(uint4*)(g_hh + i) = o;
}

// ---------------------------------------------------------------------------
// k_prep_w: g_wa[k] = sum_c W[k][c]*a1[c] (and a2); g_Wt[c][k] = fp16 W[k][c]
// 512 threads, 1 block.
// ---------------------------------------------------------------------------
__global__ void k_prep_w(const float* __restrict__ W, const float* __restrict__ a)
{
    const int tid  = threadIdx.x;
    const int lane = tid & 31;
    const int wid  = tid >> 5;       // 0..15

    // wa: warp per k row (coalesced over c)
    for (int k = wid; k < DIN; k += 16) {
        float s1 = 0.f, s2 = 0.f;
        #pragma unroll
        for (int c = lane; c < DOUT; c += 32) {
            float w = W[k * DOUT + c];
            s1 = fmaf(w, a[c], s1);
            s2 = fmaf(w, a[DOUT + c], s2);
        }
        #pragma unroll
        for (int o = 16; o; o >>= 1) {
            s1 += __shfl_xor_sync(~0u, s1, o);
            s2 += __shfl_xor_sync(~0u, s2, o);
        }
        if (lane == 0) { g_wa[k] = s1; g_wa[DIN + k] = s2; }
    }

    // Wt fp16 transpose (coalesced read, scattered 2B write: tiny)
    for (int idx = tid; idx < DIN * DOUT; idx += 512) {
        const int k = idx >> 8;          // DOUT = 256
        const int c = idx & 255;
        g_Wt[(size_t)c * DIN + k] = (unsigned short)(pack_f16x2(W[idx], 0.f) & 0xffff);
    }
}

// ---------------------------------------------------------------------------
// k_f1f2h: f1 = h @ wa1, f2 = h @ wa2  (warp per row)
// ---------------------------------------------------------------------------
__global__ void k_f1f2h(const float* __restrict__ h)
{
    const int row  = blockIdx.x * 8 + threadIdx.y;
    const int lane = threadIdx.x;
    const float* hr = h + (size_t)row * DIN;

    float s1 = 0.f, s2 = 0.f;
    #pragma unroll
    for (int k = lane; k < DIN; k += 32) {
        float v = hr[k];
        s1 = fmaf(v, g_wa[k], s1);
        s2 = fmaf(v, g_wa[DIN + k], s2);
    }
    #pragma unroll
    for (int o = 16; o; o >>= 1) {
        s1 += __shfl_xor_sync(~0u, s1, o);
        s2 += __shfl_xor_sync(~0u, s2, o);
    }
    if (lane == 0) { g_f1[row] = s1; g_f2[row] = s2; }
}

// ---------------------------------------------------------------------------
// k_fmaxE: g_fmax = max(f2); g_E[j] = (exp(f2), exp(0.2 f2))
// ---------------------------------------------------------------------------
__global__ void k_fmaxE()
{
    __shared__ float sred[32];
    const int tid = threadIdx.x;   // 1024
    float m = -1e30f;
    #pragma unroll
    for (int i = tid; i < NN; i += 1024) {
        float f2 = g_f2[i];
        m = fmaxf(m, f2);
        g_E[i] = make_float2(__expf(f2), __expf(0.2f * f2));
    }
    #pragma unroll
    for (int o = 16; o; o >>= 1) m = fmaxf(m, __shfl_xor_sync(~0u, m, o));
    if ((tid & 31) == 0) sred[tid >> 5] = m;
    __syncthreads();
    if (tid < 32) {
        float v = sred[tid];
        #pragma unroll
        for (int o = 16; o; o >>= 1) v = fmaxf(v, __shfl_xor_sync(~0u, v, o));
        if (tid == 0) g_fmax = v;
    }
}

// ---------------------------------------------------------------------------
// k_hwt: g_hWT[c][i] = fp16( h @ W )^T via fp16 tensor MMA.
// Reuses the gat tile machinery: 64(i) x 256(c), 256 thr, 8 warps 2m x 4n,
// K = 512 in 8 chunks of 64, double-buffered cp.async.
// ---------------------------------------------------------------------------
__global__ __launch_bounds__(256, 2) void k_hwt()
{
    extern __shared__ __align__(1024) char smem[];
    const uint32_t sb = smem_u32(smem);
    const int tid  = threadIdx.x;
    const int lane = tid & 31;
    const int wid  = tid >> 5;
    const int wm   = wid & 1;
    const int wn   = wid >> 1;
    const int i0   = blockIdx.x * 64;

    int AOFF[2], BOFF[2];
    #pragma unroll
    for (int s = 0; s < 2; s++) {
        AOFF[s] = TILE0 + s * STAGE_BYTES;
        BOFF[s] = AOFF[s] + 8192;
    }

    const int arow = tid >> 2, aseg = tid & 3;   // A loader
    const int rB = tid;                          // B loader (row c)

    auto load_stage = [&](int jt, int s) {
        const size_t ga = (size_t)(i0 + arow) * DIN + jt * KT + aseg * 16;
        cp16(sb + AOFF[s] + sw128((uint32_t)(arow * 128 + aseg * 32)),      g_hh + ga);
        cp16(sb + AOFF[s] + sw128((uint32_t)(arow * 128 + aseg * 32 + 16)), g_hh + ga + 8);
        const size_t gb = (size_t)rB * DIN + jt * KT;
        #pragma unroll
        for (int cc = 0; cc < 8; cc++)
            cp16(sb + BOFF[s] + sw128((uint32_t)(rB * 128 + cc * 16)), g_Wt + gb + cc * 8);
    };

    const int aRow = lane & 15;
    const int aH   = lane >> 4;
    const int bRow = (lane & 7) | ((lane >> 4) << 3);
    const int bH   = (lane >> 3) & 1;

    float acc[2][8][4];
    #pragma unroll
    for (int mt = 0; mt < 2; mt++)
        #pragma unroll
        for (int nt = 0; nt < 8; nt++)
            #pragma unroll
            for (int q = 0; q < 4; q++) acc[mt][nt][q] = 0.f;

    load_stage(0, 0);
    cp_commit();
    cp_wait0();
    __syncthreads();

    #pragma unroll 1
    for (int jt = 0; jt < HNCH; ++jt) {
        const int s = jt & 1;
        if (jt + 1 < HNCH) { load_stage(jt + 1, s ^ 1); cp_commit(); }

        #pragma unroll
        for (int kk = 0; kk < 4; kk++) {
            uint32_t ah[2][4];
            #pragma unroll
            for (int mt = 0; mt < 2; mt++)
                ldsm4(ah[mt], sb + AOFF[s] + sw128((uint32_t)(
                    (wm * 32 + mt * 16 + aRow) * 128 + kk * 32 + aH * 16)));
            uint32_t bh[4][4];
            #pragma unroll
            for (int p = 0; p < 4; p++)
                ldsm4(bh[p], sb + BOFF[s] + sw128((uint32_t)(
                    (wn * 64 + p * 16 + bRow) * 128 + kk * 32 + bH * 16)));
            #pragma unroll
            for (int mt = 0; mt < 2; mt++)
                #pragma unroll
                for (int p = 0; p < 4; p++) {
                    mma16816(acc[mt][2 * p],     ah[mt], bh[p][0], bh[p][1]);
                    mma16816(acc[mt][2 * p + 1], ah[mt], bh[p][2], bh[p][3]);
                }
        }

        if (jt + 1 < HNCH) cp_wait0();
        __syncthreads();
    }

    // ---- transpose epilogue: frags -> smem fp16 [i][c] (pitch 258) -> [c][i]
    #define TP 258
    unsigned short* buf = (unsigned short*)(smem + TILE0);
    {
        const int g  = lane >> 2;
        const int tg = lane & 3;
        #pragma unroll
        for (int mt = 0; mt < 2; mt++)
            #pragma unroll
            for (int nt = 0; nt < 8; nt++) {
                const int r0  = wm * 32 + mt * 16 + g;
                const int col = wn * 64 + nt * 8 + tg * 2;
                *(unsigned*)(buf + r0 * TP + col) =
                    pack_f16x2(acc[mt][nt][0], acc[mt][nt][1]);
                *(unsigned*)(buf + (r0 + 8) * TP + col) =
                    pack_f16x2(acc[mt][nt][2], acc[mt][nt][3]);
            }
    }
    __syncthreads();
    {
        uint32_t pk[32];
        #pragma unroll
        for (int q = 0; q < 32; q++) {
            unsigned lo = buf[(2 * q) * TP + tid];
            unsigned hi = buf[(2 * q + 1) * TP + tid];
            pk[q] = lo | (hi << 16);
        }
        unsigned short* dst = g_hWT + (size_t)tid * NN + i0;
        #pragma unroll
        for (int q = 0; q < 8; q++)
            *(uint4*)(dst + q * 8) =
                make_uint4(pk[4 * q], pk[4 * q + 1], pk[4 * q + 2], pk[4 * q + 3]);
    }
}

// ---------------------------------------------------------------------------
// k_gat_mma: R5 structure, factorized w-gen (no MUFU in loop), full K per
// CTA (no slices), fused softmax-normalize + ELU epilogue.
// w = adj ? max(c1_i * E1_j, c2_i * E2_j) : 0
//   c1 = exp(f1-M), c2 = exp(.2 f1-M), E1 = exp(f2), E2 = exp(.2 f2)
// (exp monotone + leaky(s) = max(s, .2s) => exp(leaky(s)-M) = max of products)
// ---------------------------------------------------------------------------
__global__ __launch_bounds__(256, 2) void k_gat_mma(
    const int* __restrict__ adj, float* __restrict__ out)
{
    extern __shared__ __align__(1024) char smem[];
    const uint32_t sb = smem_u32(smem);

    const int tid  = threadIdx.x;
    const int lane = tid & 31;
    const int wid  = tid >> 5;
    const int wm   = wid & 1;      // warp row  (32 rows)
    const int wn   = wid >> 1;     // warp col  (64 cols)
    const int i0   = blockIdx.x * 64;

    int AOFF[2], BOFF[2];
    #pragma unroll
    for (int s = 0; s < 2; s++) {
        AOFF[s] = TILE0 + s * STAGE_BYTES;
        BOFF[s] = AOFF[s] + 8192;
    }

    // ---- w-gen mapping: row iw, 16 k's starting at kb ----
    const int iw = tid >> 2;             // 0..63
    const int kb = (tid & 3) * 16;
    const float f1v  = g_f1[i0 + iw];
    const float smax = f1v + g_fmax;
    const float Mrow = fmaxf(smax, 0.2f * smax);
    const float c1 = __expf(f1v - Mrow);
    const float c2 = __expf(0.2f * f1v - Mrow);
    float zacc = 0.f;

    const int rB = tid;                  // B loader: row = tid

    float acc[2][8][4];
    #pragma unroll
    for (int mt = 0; mt < 2; mt++)
        #pragma unroll
        for (int nt = 0; nt < 8; nt++)
            #pragma unroll
            for (int q = 0; q < 4; q++) acc[mt][nt][q] = 0.f;

    auto load_B = [&](int jt, int s) {
        const size_t gk = (size_t)rB * NN + jt * KT;
        #pragma unroll
        for (int cc = 0; cc < 8; cc++) {
            const uint32_t off = sw128((uint32_t)(rB * 128 + cc * 16));
            cp16(sb + BOFF[s] + off, g_hWT + gk + cc * 8);
        }
    };

    auto gen_A = [&](int jt, int s) {
        const int4*   ap = (const int4*)(adj + (size_t)(i0 + iw) * NN + jt * KT + kb);
        const float4* ep = (const float4*)(g_E + jt * KT + kb);   // 2 j per float4
        int4 A0 = ap[0], A1 = ap[1], A2 = ap[2], A3 = ap[3];
        const int av[16] = {A0.x,A0.y,A0.z,A0.w, A1.x,A1.y,A1.z,A1.w,
                            A2.x,A2.y,A2.z,A2.w, A3.x,A3.y,A3.z,A3.w};
        float w[16];
        #pragma unroll
        for (int m = 0; m < 8; m++) {
            float4 e = ep[m];     // (E1_j0, E2_j0, E1_j1, E2_j1)
            float w0 = fmaxf(c1 * e.x, c2 * e.y);
            float w1 = fmaxf(c1 * e.z, c2 * e.w);
            w0 = (av[2 * m]     > 0) ? w0 : 0.f;
            w1 = (av[2 * m + 1] > 0) ? w1 : 0.f;
            zacc += w0 + w1;
            w[2 * m] = w0; w[2 * m + 1] = w1;
        }
        uint4 H0, H1;
        H0.x = pack_f16x2(w[0],  w[1]);  H0.y = pack_f16x2(w[2],  w[3]);
        H0.z = pack_f16x2(w[4],  w[5]);  H0.w = pack_f16x2(w[6],  w[7]);
        H1.x = pack_f16x2(w[8],  w[9]);  H1.y = pack_f16x2(w[10], w[11]);
        H1.z = pack_f16x2(w[12], w[13]); H1.w = pack_f16x2(w[14], w[15]);
        const uint32_t o0 = sw128((uint32_t)(iw * 128 + kb * 2));
        const uint32_t o1 = sw128((uint32_t)(iw * 128 + kb * 2 + 16));
        *(uint4*)(smem + AOFF[s] + o0) = H0;
        *(uint4*)(smem + AOFF[s] + o1) = H1;
    };

    const int aRow = lane & 15;
    const int aH   = lane >> 4;
    const int bRow = (lane & 7) | ((lane >> 4) << 3);
    const int bH   = (lane >> 3) & 1;

    // ---- prologue ----
    load_B(0, 0);
    cp_commit();
    gen_A(0, 0);
    cp_wait0();
    __syncthreads();

    #pragma unroll 1
    for (int jt = 0; jt < NCHUNK; ++jt) {
        const int s = jt & 1;
        if (jt + 1 < NCHUNK) {
            load_B(jt + 1, s ^ 1);
            cp_commit();
            gen_A(jt + 1, s ^ 1);
        }

        #pragma unroll
        for (int kk = 0; kk < 4; kk++) {
            uint32_t ah[2][4];
            #pragma unroll
            for (int mt = 0; mt < 2; mt++)
                ldsm4(ah[mt], sb + AOFF[s] + sw128((uint32_t)(
                    (wm * 32 + mt * 16 + aRow) * 128 + kk * 32 + aH * 16)));
            uint32_t bh[4][4];
            #pragma unroll
            for (int p = 0; p < 4; p++)
                ldsm4(bh[p], sb + BOFF[s] + sw128((uint32_t)(
                    (wn * 64 + p * 16 + bRow) * 128 + kk * 32 + bH * 16)));
            #pragma unroll
            for (int mt = 0; mt < 2; mt++)
                #pragma unroll
                for (int p = 0; p < 4; p++) {
                    mma16816(acc[mt][2 * p],     ah[mt], bh[p][0], bh[p][1]);
                    mma16816(acc[mt][2 * p + 1], ah[mt], bh[p][2], bh[p][3]);
                }
        }

        if (jt + 1 < NCHUNK) cp_wait0();
        __syncthreads();
    }

    // ---- epilogue: Z (complete), normalize, ELU, store ----
    float* zb = (float*)(smem + ZOFF);
    zb[tid] = zacc;
    __syncthreads();
    float* zinv = zb + 256;
    if (tid < 64)
        zinv[tid] = 1.0f / (zb[4 * tid] + zb[4 * tid + 1]
                          + zb[4 * tid + 2] + zb[4 * tid + 3]);
    __syncthreads();

    {
        const int g  = lane >> 2;
        const int tg = lane & 3;
        #pragma unroll
        for (int mt = 0; mt < 2; mt++)
            #pragma unroll
            for (int nt = 0; nt < 8; nt++) {
                const int r0  = wm * 32 + mt * 16 + g;
                const int col = wn * 64 + nt * 8 + tg * 2;
                const float zi0 = zinv[r0];
                const float zi1 = zinv[r0 + 8];
                float v0 = acc[mt][nt][0] * zi0;
                float v1 = acc[mt][nt][1] * zi0;
                float v2 = acc[mt][nt][2] * zi1;
                float v3 = acc[mt][nt][3] * zi1;
                v0 = (v0 > 0.f) ? v0 : expm1f(v0);
                v1 = (v1 > 0.f) ? v1 : expm1f(v1);
                v2 = (v2 > 0.f) ? v2 : expm1f(v2);
                v3 = (v3 > 0.f) ? v3 : expm1f(v3);
                *(float2*)(out + (size_t)(i0 + r0) * DOUT + col)     = make_float2(v0, v1);
                *(float2*)(out + (size_t)(i0 + r0 + 8) * DOUT + col) = make_float2(v2, v3);
            }
    }
}

// ---------------------------------------------------------------------------
extern "C" void kernel_launch(void* const* d_in, const int* in_sizes, int n_in,
                              void* d_out, int out_size)
{
    const float* h   = (const float*)d_in[0];   // [8192, 512]
    const int*   adj = (const int*)  d_in[1];   // [8192, 8192]
    const float* W   = (const float*)d_in[2];   // [512, 256]
    const float* a   = (const float*)d_in[3];   // [512, 1]
    float* out = (float*)d_out;                 // [8192, 256]

    cudaFuncSetAttribute(k_hwt, cudaFuncAttributeMaxDynamicSharedMemorySize,
                         SMEM_TOTAL);
    cudaFuncSetAttribute(k_gat_mma, cudaFuncAttributeMaxDynamicSharedMemorySize,
                         SMEM_TOTAL);

    k_conv_h<<<NN * DIN / (256 * 8), 256>>>(h);
    k_prep_w<<<1, 512>>>(W, a);
    k_f1f2h<<<NN / 8, dim3(32, 8)>>>(h);
    k_fmaxE<<<1, 1024>>>();
    k_hwt<<<NN / 64, 256, SMEM_TOTAL>>>();
    k_gat_mma<<<NN / 64, 256, SMEM_TOTAL>>>(adj, out);
}